// round 15
// baseline (speedup 1.0000x reference)
#include <cuda_runtime.h>
#include <cuda_bf16.h>
#include <cuda_fp16.h>
#include <math.h>
#include <stdint.h>
#include <float.h>

#define BSZ   8192
#define MDIM  128
#define NDIM  128
#define KDIM  256
#define MN    16384

// -------- device scratch --------
__device__ __align__(16) float g_wsq[MN];
__device__ float g_sched[2];           // [0] = 2*sigma^2, [1] = lr
__device__ __align__(16) __half g_pxTh[MDIM * BSZ];  // px fp16 [m][b]
__device__ __align__(16) __half g_pyTh[NDIM * BSZ];  // py*lr fp16 [n][b]
// blocked, pre-swizzled tiles (32KB blocks, bulk-copy sources)
__device__ __align__(128) char g_wblk[MN * KDIM * 2];    // W hi: 256 blocks
__device__ __align__(128) char g_xbk[BSZ * KDIM * 2];    // X hi row-major: 128 blocks
__device__ __align__(128) char g_xbhi[KDIM * BSZ * 2];   // X^T hi: 128 blocks
__device__ __align__(128) char g_xblo[KDIM * BSZ * 2];   // X^T lo: 128 blocks
__device__ int   g_cj[4 * BSZ * 2];    // top-2 candidate j per (quarter, b)
__device__ int   g_bmu[BSZ];

extern __shared__ float sm[];

__device__ __forceinline__ uint32_t smem_u32(const void* p) {
    uint32_t a;
    asm("{ .reg .u64 t; cvta.to.shared.u64 t, %1; cvt.u32.u64 %0, t; }"
        : "=r"(a) : "l"(p));
    return a;
}
__device__ __forceinline__ uint32_t pk2h(__half a, __half b) {
    __half2 t = __halves2half2(a, b);
    return *reinterpret_cast<uint32_t*>(&t);
}
__device__ __forceinline__ void mma_f16(float* d,
                                        uint32_t a0, uint32_t a1,
                                        uint32_t a2, uint32_t a3,
                                        uint32_t b0, uint32_t b1) {
    asm volatile(
        "mma.sync.aligned.m16n8k16.row.col.f32.f16.f16.f32 "
        "{%0,%1,%2,%3}, {%4,%5,%6,%7}, {%8,%9}, {%0,%1,%2,%3};"
        : "+f"(d[0]), "+f"(d[1]), "+f"(d[2]), "+f"(d[3])
        : "r"(a0), "r"(a1), "r"(a2), "r"(a3), "r"(b0), "r"(b1));
}
__device__ __forceinline__ void ldsm_x4(uint32_t& r0, uint32_t& r1,
                                        uint32_t& r2, uint32_t& r3,
                                        uint32_t addr) {
    asm volatile("ldmatrix.sync.aligned.m8n8.x4.shared.b16 {%0,%1,%2,%3}, [%4];"
                 : "=r"(r0), "=r"(r1), "=r"(r2), "=r"(r3) : "r"(addr));
}
// ---- bulk copy + mbarrier ----
__device__ __forceinline__ void bulk_g2s(uint32_t dst, const void* src,
                                         uint32_t bytes, uint32_t mbar) {
    asm volatile(
        "cp.async.bulk.shared::cta.global.mbarrier::complete_tx::bytes "
        "[%0], [%1], %2, [%3];"
        :: "r"(dst), "l"(src), "r"(bytes), "r"(mbar) : "memory");
}
__device__ __forceinline__ void mbar_init(uint32_t a, uint32_t cnt) {
    asm volatile("mbarrier.init.shared.b64 [%0], %1;" :: "r"(a), "r"(cnt) : "memory");
}
__device__ __forceinline__ void mbar_expect(uint32_t a, uint32_t bytes) {
    asm volatile("mbarrier.arrive.expect_tx.shared.b64 _, [%0], %1;"
                 :: "r"(a), "r"(bytes) : "memory");
}
__device__ __forceinline__ void mbar_wait(uint32_t a, uint32_t parity) {
    asm volatile(
        "{\n\t.reg .pred P1;\n\t"
        "W_%=:\n\t"
        "mbarrier.try_wait.parity.acquire.cta.shared::cta.b64 P1, [%0], %1, 0x989680;\n\t"
        "@P1 bra.uni D_%=;\n\t"
        "bra.uni W_%=;\n\t"
        "D_%=:\n\t}"
        :: "r"(a), "r"(parity) : "memory");
}

__device__ __forceinline__ void t2_ins(float z, int j,
                                       float& z1, int& j1, float& z2, int& j2) {
    if (z < z1) { z2 = z1; j2 = j1; z1 = z; j1 = j; }
    else if (z < z2) { z2 = z; j2 = j; }
}
__device__ __forceinline__ void top2_merge(float& z1, int& j1, float& z2, int& j2,
                                           float oz1, int oj1, float oz2, int oj2) {
    bool b1 = (oz1 < z1) || (oz1 == z1 && oj1 < j1);
    if (b1) {
        bool b2 = (z1 < oz2) || (z1 == oz2 && j1 < oj2);
        z2 = b2 ? z1 : oz2; j2 = b2 ? j1 : oj2;
        z1 = oz1; j1 = oj1;
    } else {
        bool b2 = (oz1 < z2) || (oz1 == z2 && oj1 < j2);
        z2 = b2 ? oz1 : z2; j2 = b2 ? oj1 : j2;
    }
}

// ============================================================
// Kernel 1: W only. Warp per row: wsq + fp16 blocked swizzled copy.
// ============================================================
__global__ void ker_wx(const float* __restrict__ W,
                       const int*  __restrict__ itp) {
    if (blockIdx.x == 0 && threadIdx.x == 0) {
        int it = itp[0];
        double TAU   = 20.0 / log(64.0);
        double sigma = 64.0 * exp(-(double)it / TAU);
        g_sched[0] = (float)(2.0 * sigma * sigma);
        g_sched[1] = (float)(0.5 * exp(-(double)it / 20.0));
    }
    int warp = (blockIdx.x * blockDim.x + threadIdx.x) >> 5;
    int lane = threadIdx.x & 31;
    if (warp >= MN) return;

    const float* src = W + (size_t)warp * KDIM;
    float4 v0 = *(const float4*)(src + lane * 8);
    float4 v1 = *(const float4*)(src + lane * 8 + 4);
    uint4 hv;
    hv.x = pk2h(__float2half_rn(v0.x), __float2half_rn(v0.y));
    hv.y = pk2h(__float2half_rn(v0.z), __float2half_rn(v0.w));
    hv.z = pk2h(__float2half_rn(v1.x), __float2half_rn(v1.y));
    hv.w = pk2h(__float2half_rn(v1.z), __float2half_rn(v1.w));

    int jr = warp & 127;
    int bid = (warp >> 7) * 2 + (lane >> 4);
    int col16 = lane & 15;
    int sw = col16 ^ (jr & 7);
    *(uint4*)(g_wblk + (size_t)bid * 32768 + jr * 256 + sw * 16) = hv;
    float s = v0.x*v0.x + v0.y*v0.y + v0.z*v0.z + v0.w*v0.w
            + v1.x*v1.x + v1.y*v1.y + v1.z*v1.z + v1.w*v1.w;
#pragma unroll
    for (int o = 16; o > 0; o >>= 1) s += __shfl_down_sync(0xffffffffu, s, o);
    if (lane == 0) g_wsq[warp] = s;
}

// ============================================================
// Kernel 1c: X -> (a) transposed split-fp16 blocked (numer) and
// (b) row-major fp16 blocked (dist), both pre-swizzled.
// ============================================================
__global__ void ker_prep(const float* __restrict__ X) {
    __shared__ float t[64][65];
    int bt = blockIdx.x;          // b block (64)
    int dt = blockIdx.y;          // d quarter (64)
    int tid = threadIdx.x;
#pragma unroll
    for (int s = 0; s < 16; s++) {
        int e = tid + 256 * s;
        int b = e >> 6, d = e & 63;
        t[b][d] = X[(size_t)(bt * 64 + b) * KDIM + dt * 64 + d];
    }
    __syncthreads();

    // (a) transposed hi/lo for numer
    char* bhi = g_xbhi + (size_t)bt * 32768;
    char* blo = g_xblo + (size_t)bt * 32768;
#pragma unroll
    for (int s = 0; s < 8; s++) {
        int p = tid + 256 * s;
        int d = p >> 5, bp = p & 31;
        float a0 = t[bp * 2][d], a1 = t[bp * 2 + 1][d];
        __half h0 = __float2half_rn(a0);
        __half h1 = __float2half_rn(a1);
        __half l0 = __float2half_rn(a0 - __half2float(h0));
        __half l1 = __float2half_rn(a1 - __half2float(h1));
        int dg = dt * 64 + d;
        int br = bp * 2;
        uint32_t off = dg * 128 + (((br >> 3) ^ (dg & 7)) << 4) + (br & 7) * 2;
        *(uint32_t*)(bhi + off) = pk2h(h0, h1);
        *(uint32_t*)(blo + off) = pk2h(l0, l1);
    }

    // (b) row-major fp16 blocked for dist (512B rows, XOR-swizzled)
    char* bxk = g_xbk + (size_t)bt * 32768;
#pragma unroll
    for (int s = 0; s < 2; s++) {
        int i = tid + 256 * s;           // 512 items: 64 b x 8 col16-local
        int b = i >> 3, c8 = i & 7;
        const float* tr = &t[b][c8 * 8];
        uint4 hv;
        hv.x = pk2h(__float2half_rn(tr[0]), __float2half_rn(tr[1]));
        hv.y = pk2h(__float2half_rn(tr[2]), __float2half_rn(tr[3]));
        hv.z = pk2h(__float2half_rn(tr[4]), __float2half_rn(tr[5]));
        hv.w = pk2h(__float2half_rn(tr[6]), __float2half_rn(tr[7]));
        int col16 = dt * 8 + c8;
        *(uint4*)(bxk + b * 512 + ((col16 ^ (b & 7)) << 4)) = hv;
    }
}

// ============================================================
// Kernel 2: approx distance GEMM (hh-only fp16 HMMA) + top-2.
// X tile AND W chunks via cp.async.bulk; XOR-swizzled, no pads.
// ============================================================
#define XS_ROW    512
#define OFF_WBUF  (256 * XS_ROW)             // 131072
#define WSTAGE    32768
#define OFF_WSQ   (OFF_WBUF + 2 * WSTAGE)    // 196608
#define OFF_MBAR  (OFF_WSQ + 16384)          // 212992 (3 barriers)
#define DIST_SMEM (OFF_MBAR + 64)            // 213056

__global__ void __launch_bounds__(512, 1)
ker_dist_mma() {
    char* base = (char*)sm;
    uint32_t sbase = smem_u32(base);
    const int tid  = threadIdx.x;
    const int lane = tid & 31;
    const int wid  = tid >> 5;
    const int wb   = wid >> 2;
    const int wj   = wid & 3;
    const int g    = lane >> 2;
    const int c2   = (lane & 3) * 2;
    const int bblk = blockIdx.x * 4;          // 4 x 64-row X blocks
    const int b0   = blockIdx.x * 256;
    const int quar = blockIdx.y;
    const int jbase = quar * 4096;

    const int la15 = lane & 15;
    const int laKA16 = lane >> 4;             // A col16 low bit
    const int laRB = (lane & 7) + ((lane >> 4) << 3);
    const int laKB16 = (lane >> 3) & 1;       // B col16 low bit

    if (tid == 0) {
        mbar_init(sbase + OFF_MBAR, 1);       // W buf 0
        mbar_init(sbase + OFF_MBAR + 8, 1);   // W buf 1
        mbar_init(sbase + OFF_MBAR + 16, 1);  // X tile
    }
    // wsq slice via regular loads (overlaps with bulk)
#pragma unroll
    for (int t = 0; t < 2; t++) {
        int i = tid + 512 * t;
        *(uint4*)(base + OFF_WSQ + i * 16) =
            *(const uint4*)((const char*)(g_wsq + jbase) + i * 16);
    }
    const float* swsq = (const float*)(base + OFF_WSQ);
    __syncthreads();     // mbar init visible

    if (tid == 0) {
        uint32_t mbx = sbase + OFF_MBAR + 16;
        mbar_expect(mbx, 4 * 32768);
#pragma unroll
        for (int i = 0; i < 4; i++)
            bulk_g2s(sbase + (uint32_t)i * 32768,
                     g_xbk + (size_t)(bblk + i) * 32768, 32768, mbx);
        uint32_t mb = sbase + OFF_MBAR;
        mbar_expect(mb, WSTAGE);
        bulk_g2s(sbase + OFF_WBUF, g_wblk + (size_t)(quar * 64) * WSTAGE,
                 WSTAGE, mb);
    }

    float z1[8], z2[8];
    int   j1[8], j2[8];
#pragma unroll
    for (int i = 0; i < 8; i++) { z1[i] = z2[i] = FLT_MAX; j1[i] = j2[i] = MN; }

    mbar_wait(sbase + OFF_MBAR + 16, 0);   // X tile ready

    float acc[4][4][4];

    for (int ci = 0; ci < 64; ci++) {
        const int jt = ci >> 1, kc = ci & 1;

        mbar_wait(sbase + OFF_MBAR + (uint32_t)(ci & 1) * 8, (ci >> 1) & 1);
        __syncthreads();
        if (tid == 0 && ci + 1 < 64) {
            uint32_t mb = sbase + OFF_MBAR + (uint32_t)((ci + 1) & 1) * 8;
            mbar_expect(mb, WSTAGE);
            bulk_g2s(sbase + OFF_WBUF + (uint32_t)((ci + 1) & 1) * WSTAGE,
                     g_wblk + (size_t)(quar * 64 + ci + 1) * WSTAGE, WSTAGE, mb);
        }

        if (kc == 0) {
#pragma unroll
            for (int bt = 0; bt < 4; bt++)
#pragma unroll
                for (int nt = 0; nt < 4; nt++)
#pragma unroll
                    for (int r = 0; r < 4; r++) acc[bt][nt][r] = 0.f;
        }

        const uint32_t wboff = sbase + OFF_WBUF + (uint32_t)(ci & 1) * WSTAGE;
#pragma unroll
        for (int ks = 0; ks < 8; ks++) {
            uint32_t ah[4][4];
            const int col16A = kc * 16 + ks * 2 + laKA16;
#pragma unroll
            for (int bt = 0; bt < 4; bt++) {
                int row = wb * 64 + bt * 16 + la15;
                uint32_t ra = sbase + row * XS_ROW
                            + (uint32_t)((col16A ^ (row & 7)) << 4);
                ldsm_x4(ah[bt][0], ah[bt][1], ah[bt][2], ah[bt][3], ra);
            }
            uint32_t bh[2][4];
            const int col16B = ks * 2 + laKB16;
#pragma unroll
            for (int ntp = 0; ntp < 2; ntp++) {
                int row = wj * 32 + ntp * 16 + laRB;
                uint32_t rb = wboff + row * 256 + (uint32_t)((col16B ^ (row & 7)) << 4);
                ldsm_x4(bh[ntp][0], bh[ntp][1], bh[ntp][2], bh[ntp][3], rb);
            }
#pragma unroll
            for (int ntp = 0; ntp < 2; ntp++)
#pragma unroll
                for (int bt = 0; bt < 4; bt++) {
                    mma_f16(acc[bt][ntp*2],   ah[bt][0], ah[bt][1], ah[bt][2], ah[bt][3], bh[ntp][0], bh[ntp][1]);
                    mma_f16(acc[bt][ntp*2+1], ah[bt][0], ah[bt][1], ah[bt][2], ah[bt][3], bh[ntp][2], bh[ntp][3]);
                }
        }

        if (kc == 1) {
            const int j0 = jt * 128 + wj * 32;
#pragma unroll
            for (int nt = 0; nt < 4; nt++) {
                int jg = j0 + nt * 8 + c2;
                float w0 = swsq[jg];
                float w1 = swsq[jg + 1];
#pragma unroll
                for (int bt = 0; bt < 4; bt++) {
                    float za0 = fmaf(-2.f, acc[bt][nt][0], w0);
                    float zb0 = fmaf(-2.f, acc[bt][nt][1], w1);
                    float za1 = fmaf(-2.f, acc[bt][nt][2], w0);
                    float zb1 = fmaf(-2.f, acc[bt][nt][3], w1);
                    int s0 = bt * 2, s1 = bt * 2 + 1;
                    if (fminf(za0, zb0) < z2[s0]) {
                        t2_ins(za0, jg,     z1[s0], j1[s0], z2[s0], j2[s0]);
                        t2_ins(zb0, jg + 1, z1[s0], j1[s0], z2[s0], j2[s0]);
                    }
                    if (fminf(za1, zb1) < z2[s1]) {
                        t2_ins(za1, jg,     z1[s1], j1[s1], z2[s1], j2[s1]);
                        t2_ins(zb1, jg + 1, z1[s1], j1[s1], z2[s1], j2[s1]);
                    }
                }
            }
        }
    }

#pragma unroll
    for (int i = 0; i < 8; i++) {
#pragma unroll
        for (int off = 1; off <= 2; off <<= 1) {
            float oz1 = __shfl_xor_sync(0xffffffffu, z1[i], off);
            int   oj1 = __shfl_xor_sync(0xffffffffu, j1[i], off);
            float oz2 = __shfl_xor_sync(0xffffffffu, z2[i], off);
            int   oj2 = __shfl_xor_sync(0xffffffffu, j2[i], off);
            top2_merge(z1[i], j1[i], z2[i], j2[i], oz1, oj1, oz2, oj2);
        }
    }

    __syncthreads();
    float* sz1 = (float*)(base + OFF_WBUF);
    int*   sj1 = (int*)(base + OFF_WBUF + 4096);
    float* sz2 = (float*)(base + OFF_WBUF + 8192);
    int*   sj2 = (int*)(base + OFF_WBUF + 12288);
    if ((lane & 3) == 0) {
#pragma unroll
        for (int i = 0; i < 8; i++) {
            int bt = i >> 1, h = i & 1;
            int row = wb * 64 + bt * 16 + g + 8 * h;
            sz1[row * 4 + wj] = z1[i];
            sj1[row * 4 + wj] = j1[i];
            sz2[row * 4 + wj] = z2[i];
            sj2[row * 4 + wj] = j2[i];
        }
    }
    __syncthreads();
    if (tid < 256) {
        float a1 = sz1[tid * 4], a2 = sz2[tid * 4];
        int   i1 = sj1[tid * 4], i2 = sj2[tid * 4];
        for (int t = 1; t < 4; t++)
            top2_merge(a1, i1, a2, i2,
                       sz1[tid * 4 + t], sj1[tid * 4 + t],
                       sz2[tid * 4 + t], sj2[tid * 4 + t]);
        int gb = quar * BSZ + b0 + tid;
        g_cj[gb * 2]     = jbase + i1;
        g_cj[gb * 2 + 1] = jbase + i2;
    }
}

// ============================================================
// Kernel 2b: exact fp32 re-evaluation of <=8 BMU candidates.
// ============================================================
__global__ void ker_fix(const float* __restrict__ X,
                        const float* __restrict__ W) {
    int b    = blockIdx.x * 8 + (threadIdx.x >> 5);
    int lane = threadIdx.x & 31;

    int cand[8];
#pragma unroll
    for (int q = 0; q < 4; q++) {
        cand[q * 2]     = g_cj[((size_t)q * BSZ + b) * 2];
        cand[q * 2 + 1] = g_cj[((size_t)q * BSZ + b) * 2 + 1];
    }

    const float* xb = X + (size_t)b * KDIM;
    float x[8];
#pragma unroll
    for (int t = 0; t < 8; t++) x[t] = xb[lane * 8 + t];

    float bestz = FLT_MAX;
    int   bestj = MN;
#pragma unroll
    for (int c = 0; c < 8; c++) {
        int j = cand[c];
        const float* wj = W + (size_t)j * KDIM;
        float s = 0.f;
#pragma unroll
        for (int t = 0; t < 8; t++) s += x[t] * wj[lane * 8 + t];
#pragma unroll
        for (int o = 16; o > 0; o >>= 1) s += __shfl_down_sync(0xffffffffu, s, o);
        if (lane == 0) {
            float z = fmaf(-2.f, s, g_wsq[j]);
            if (z < bestz || (z == bestz && j < bestj)) { bestz = z; bestj = j; }
        }
    }
    if (lane == 0) g_bmu[b] = bestj;
}

// ============================================================
// Kernel 3: neighborhood factors (fp16) from exact BMU
// ============================================================
__global__ void ker_pxpy() {
    int i = blockIdx.x;
    float d  = g_sched[0];
    float lr = g_sched[1];
    float fi = (float)i;
    for (int b = threadIdx.x; b < BSZ; b += 256) {
        int bmu = g_bmu[b];
        float dr = fi - (float)(bmu >> 7);
        float dc = fi - (float)(bmu & 127);
        g_pxTh[(size_t)i * BSZ + b] = __float2half_rn(expf(-(dr * dr) / d));
        g_pyTh[(size_t)i * BSZ + b] = __float2half_rn(lr * expf(-(dc * dc) / d));
    }
}

// ============================================================
// Kernel 4: numer (fp16 HMMA, 2 terms) + fused denom.
// (unchanged from R14)
// ============================================================
#define N_ROWA   144
#define N_ABUF   (128 * N_ROWA)
#define XBLK     32768
#define N_XBUF   (2 * XBLK)
#define OFF_DSUM 0
#define OFF_NMB  512
#define OFF_A0   1024
#define OFF_X0   (OFF_A0 + 2 * N_ABUF)
#define NUMER_SMEM (OFF_X0 + 2 * N_XBUF)     // 168960

__global__ void __launch_bounds__(512, 1)
ker_numer_tc(const float* __restrict__ Wold, float* __restrict__ OUT) {
    char* base = (char*)sm;
    uint32_t sbase = smem_u32(base);
    float* dsum = (float*)(base + OFF_DSUM);

    const int tid  = threadIdx.x;
    const int wid  = tid >> 5;
    const int lane = tid & 31;
    const int m    = blockIdx.x;

    const int n0 = (wid >> 2) * 32;
    const int d0 = (wid & 3) * 64;
    const int g  = lane >> 2;
    const int c2 = (lane & 3) * 2;

    const int la15 = lane & 15;
    const int laKA = (lane >> 4) << 4;
    const int laRB = (lane & 7) + ((lane >> 4) << 3);
    const int laKB16 = (lane >> 3) & 1;

    if (tid < 128) dsum[tid] = 0.f;
    if (tid == 0) {
        mbar_init(sbase + OFF_NMB, 1);
        mbar_init(sbase + OFF_NMB + 8, 1);
    }

    float acc[2][8][4];
#pragma unroll
    for (int mt = 0; mt < 2; mt++)
#pragma unroll
        for (int nt = 0; nt < 8; nt++)
#pragma unroll
            for (int r = 0; r < 4; r++) acc[mt][nt][r] = 0.f;

    const int bg = tid & 7;
    const int nrow = tid >> 3;
    float dden[2] = {0.f, 0.f};

#define NUMER_XISSUE(ch) do {                                                  \
        uint32_t mb = sbase + OFF_NMB + (uint32_t)((ch) & 1) * 8;              \
        uint32_t xb = sbase + OFF_X0 + (uint32_t)((ch) & 1) * N_XBUF;          \
        mbar_expect(mb, 2 * XBLK);                                             \
        bulk_g2s(xb,        g_xbhi + (size_t)(ch) * XBLK, XBLK, mb);           \
        bulk_g2s(xb + XBLK, g_xblo + (size_t)(ch) * XBLK, XBLK, mb);           \
    } while (0)

#define NUMER_LDG(ch, pxv, py0, py1) do {                                      \
        size_t bo = (size_t)((ch) * 64 + bg * 8) * 2;                          \
        pxv = *(const uint4*)((const char*)(g_pxTh + (size_t)m * BSZ) + bo);   \
        py0 = *(const uint4*)((const char*)(g_pyTh + (size_t)nrow * BSZ) + bo);\
        py1 = *(const uint4*)((const char*)(g_pyTh + (size_t)(nrow + 64) * BSZ) + bo); \
    } while (0)

#define NUMER_CONVERT(ch, pxv, py0, py1) do {                                  \
        uint32_t ab = (uint32_t)(OFF_A0 + ((ch) & 1) * N_ABUF);                \
        __half2* pxh = (__half2*)&(pxv);                                       \
        float2 pf[4];                                                          \
        _Pragma("unroll")                                                      \
        for (int k = 0; k < 4; k++) pf[k] = __half22float2(pxh[k]);            \
        _Pragma("unroll")                                                      \
        for (int s = 0; s < 2; s++) {                                          \
            int n = nrow + 64 * s;                                             \
            uint4 pv = s ? (py1) : (py0);                                      \
            __half2* ph = (__half2*)&pv;                                       \
            float ssum = 0.f;                                                  \
            __half h[8];                                                       \
            _Pragma("unroll")                                                  \
            for (int k = 0; k < 4; k++) {                                      \
                float2 yf = __half22float2(ph[k]);                             \
                float a0 = pf[k].x * yf.x;                                     \
                float a1 = pf[k].y * yf.y;                                     \
                h[2*k]   = __float2half_rn(a0);                                \
                h[2*k+1] = __float2half_rn(a1);                                \
                ssum += __half2float(h[2*k]) + __half2float(h[2*k+1]);         \
            }                                                                  \
            dden[s] += ssum;                                                   \
            uint4 hv = make_uint4(pk2h(h[0],h[1]), pk2h(h[2],h[3]),            \
                                  pk2h(h[4],h[5]), pk2h(h[6],h[7]));           \
            *(uint4*)(base + ab + n * N_ROWA + bg * 16) = hv;                  \
        }                                                                      \
    } while (0)

    {
        uint4 pxv, py0, py1;
        NUMER_LDG(0, pxv, py0, py1);
        NUMER_CONVERT(0, pxv, py0, py1);
        __syncthreads();
        if (tid == 0) NUMER_XISSUE(0);
    }

    uint4 pxv, py0, py1;
    for (int ch = 0; ch < 128; ch++) {
        mbar_wait(sbase + OFF_NMB + (uint32_t)(ch & 1) * 8, (ch >> 1) & 1);
        __syncthreads();

        const bool more = (ch + 1 < 128);
        if (more) {
            if (tid == 0) NUMER_XISSUE(ch + 1);
            NUMER_LDG(ch + 1, pxv, py0, py1);
        }

        const uint32_t abase = sbase + OFF_A0 + (uint32_t)(ch & 1) * N_ABUF;
        const uint32_t xbase = sbase + OFF_X0 + (uint32_t)(ch & 1) * N_XBUF;
#pragma unroll
        for (int ks = 0; ks < 4; ks++) {
            uint32_t ah[2][4];
            const int kbA = ks * 32 + laKA;
#pragma unroll
            for (int bt = 0; bt < 2; bt++) {
                uint32_t ra = abase + (n0 + bt * 16 + la15) * N_ROWA + kbA;
                ldsm_x4(ah[bt][0], ah[bt][1], ah[bt][2], ah[bt][3], ra);
            }
            const int col16 = ks * 2 + laKB16;
#pragma unroll
            for (int h2 = 0; h2 < 2; h2++) {
                uint32_t bh[2][4], bl[2][4];
#pragma unroll
                for (int p = 0; p < 2; p++) {
                    int row = d0 + (h2 * 2 + p) * 16 + laRB;
                    uint32_t sw = (uint32_t)((col16 ^ (row & 7)) << 4);
                    uint32_t rb = xbase + row * 128 + sw;
                    ldsm_x4(bh[p][0], bh[p][1], bh[p][2], bh[p][3], rb);
                    ldsm_x4(bl[p][0], bl[p][1], bl[p][2], bl[p][3], rb + XBLK);
                }
#pragma unroll
                for (int p = 0; p < 2; p++)
#pragma unroll
                    for (int bt = 0; bt < 2; bt++) {
                        int nt = (h2 * 2 + p) * 2;
                        mma_f16(acc[bt][nt],   ah[bt][0], ah[bt][1], ah[bt][2], ah[bt][3], bh[p][0], bh[p][1]);
                        mma_f16(acc[bt][nt+1], ah[bt][0], ah[bt][1], ah[bt][2], ah[bt][3], bh[p][2], bh[p][3]);
                    }
#pragma unroll
                for (int p = 0; p < 2; p++)
#pragma unroll
                    for (int bt = 0; bt < 2; bt++) {
                        int nt = (h2 * 2 + p) * 2;
                        mma_f16(acc[bt][nt],   ah[bt][0], ah[bt][1], ah[bt][2], ah[bt][3], bl[p][0], bl[p][1]);
                        mma_f16(acc[bt][nt+1], ah[bt][0], ah[bt][1], ah[bt][2], ah[bt][3], bl[p][2], bl[p][3]);
                    }
            }
        }

        if (more) NUMER_CONVERT(ch + 1, pxv, py0, py1);
    }

    __syncthreads();
#pragma unroll
    for (int s = 0; s < 2; s++)
        atomicAdd(&dsum[nrow + 64 * s], dden[s]);
    __syncthreads();

#pragma unroll
    for (int mt = 0; mt < 2; mt++) {
#pragma unroll
        for (int gg = 0; gg < 2; gg++) {
            int n = n0 + mt * 16 + g + gg * 8;
            float den = dsum[n];
            size_t rb = ((size_t)(m * 128 + n)) * KDIM;
#pragma unroll
            for (int nt = 0; nt < 8; nt++) {
                int dcol = d0 + nt * 8 + c2;
                float v0 = acc[mt][nt][gg * 2];
                float v1 = acc[mt][nt][gg * 2 + 1];
                float2 o;
                if (den != 0.f) {
                    o.x = v0 / den; o.y = v1 / den;
                } else {
                    o.x = Wold[rb + dcol]; o.y = Wold[rb + dcol + 1];
                }
                *(float2*)(OUT + rb + dcol) = o;
            }
        }
    }
}

// ============================================================
extern "C" void kernel_launch(void* const* d_in, const int* in_sizes, int n_in,
                              void* d_out, int out_size) {
    (void)in_sizes; (void)n_in; (void)out_size;
    const float* data    = (const float*)d_in[0];
    const float* weights = (const float*)d_in[1];
    const int*   itp     = (const int*)d_in[2];
    float*       out     = (float*)d_out;

    cudaFuncSetAttribute(ker_dist_mma, cudaFuncAttributeMaxDynamicSharedMemorySize,
                         DIST_SMEM);
    cudaFuncSetAttribute(ker_numer_tc, cudaFuncAttributeMaxDynamicSharedMemorySize,
                         NUMER_SMEM);

    ker_wx<<<MN / 8, 256>>>(weights, itp);
    ker_prep<<<dim3(BSZ / 64, KDIM / 64), 256>>>(data);
    ker_dist_mma<<<dim3(32, 4), 512, DIST_SMEM>>>();
    ker_fix<<<BSZ / 8, 256>>>(data, weights);
    ker_pxpy<<<128, 256>>>();
    ker_numer_tc<<<128, 512, NUMER_SMEM>>>(weights, out);
}

// round 16
// speedup vs baseline: 1.2829x; 1.2829x over previous
#include <cuda_runtime.h>
#include <cuda_bf16.h>
#include <cuda_fp16.h>
#include <math.h>
#include <stdint.h>
#include <float.h>

#define BSZ   8192
#define MDIM  128
#define NDIM  128
#define KDIM  256
#define MN    16384

// -------- device scratch --------
__device__ __align__(16) float g_wsq[MN];
__device__ float g_sched[2];           // [0] = 2*sigma^2, [1] = lr
__device__ __align__(16) __half g_pxTh[MDIM * BSZ];  // px fp16 [m][b]
__device__ __align__(16) __half g_pyTh[NDIM * BSZ];  // py*lr fp16 [n][b]
// blocked, pre-swizzled tiles (32KB blocks, bulk-copy sources)
__device__ __align__(128) char g_wblk[MN * KDIM * 2];    // W hi: 256 blocks
__device__ __align__(128) char g_xbk[BSZ * KDIM * 2];    // X hi row-major: 128 blocks
__device__ __align__(128) char g_xbhi[KDIM * BSZ * 2];   // X^T hi: 128 blocks
__device__ int   g_cj[4 * BSZ * 2];    // top-2 candidate j per (quarter, b)
__device__ int   g_bmu[BSZ];

extern __shared__ float sm[];

__device__ __forceinline__ uint32_t smem_u32(const void* p) {
    uint32_t a;
    asm("{ .reg .u64 t; cvta.to.shared.u64 t, %1; cvt.u32.u64 %0, t; }"
        : "=r"(a) : "l"(p));
    return a;
}
__device__ __forceinline__ uint32_t pk2h(__half a, __half b) {
    __half2 t = __halves2half2(a, b);
    return *reinterpret_cast<uint32_t*>(&t);
}
__device__ __forceinline__ void mma_f16(float* d,
                                        uint32_t a0, uint32_t a1,
                                        uint32_t a2, uint32_t a3,
                                        uint32_t b0, uint32_t b1) {
    asm volatile(
        "mma.sync.aligned.m16n8k16.row.col.f32.f16.f16.f32 "
        "{%0,%1,%2,%3}, {%4,%5,%6,%7}, {%8,%9}, {%0,%1,%2,%3};"
        : "+f"(d[0]), "+f"(d[1]), "+f"(d[2]), "+f"(d[3])
        : "r"(a0), "r"(a1), "r"(a2), "r"(a3), "r"(b0), "r"(b1));
}
__device__ __forceinline__ void ldsm_x4(uint32_t& r0, uint32_t& r1,
                                        uint32_t& r2, uint32_t& r3,
                                        uint32_t addr) {
    asm volatile("ldmatrix.sync.aligned.m8n8.x4.shared.b16 {%0,%1,%2,%3}, [%4];"
                 : "=r"(r0), "=r"(r1), "=r"(r2), "=r"(r3) : "r"(addr));
}
// ---- bulk copy + mbarrier ----
__device__ __forceinline__ void bulk_g2s(uint32_t dst, const void* src,
                                         uint32_t bytes, uint32_t mbar) {
    asm volatile(
        "cp.async.bulk.shared::cta.global.mbarrier::complete_tx::bytes "
        "[%0], [%1], %2, [%3];"
        :: "r"(dst), "l"(src), "r"(bytes), "r"(mbar) : "memory");
}
__device__ __forceinline__ void mbar_init(uint32_t a, uint32_t cnt) {
    asm volatile("mbarrier.init.shared.b64 [%0], %1;" :: "r"(a), "r"(cnt) : "memory");
}
__device__ __forceinline__ void mbar_expect(uint32_t a, uint32_t bytes) {
    asm volatile("mbarrier.arrive.expect_tx.shared.b64 _, [%0], %1;"
                 :: "r"(a), "r"(bytes) : "memory");
}
__device__ __forceinline__ void mbar_wait(uint32_t a, uint32_t parity) {
    asm volatile(
        "{\n\t.reg .pred P1;\n\t"
        "W_%=:\n\t"
        "mbarrier.try_wait.parity.acquire.cta.shared::cta.b64 P1, [%0], %1, 0x989680;\n\t"
        "@P1 bra.uni D_%=;\n\t"
        "bra.uni W_%=;\n\t"
        "D_%=:\n\t}"
        :: "r"(a), "r"(parity) : "memory");
}

__device__ __forceinline__ void t2_ins(float z, int j,
                                       float& z1, int& j1, float& z2, int& j2) {
    if (z < z1) { z2 = z1; j2 = j1; z1 = z; j1 = j; }
    else if (z < z2) { z2 = z; j2 = j; }
}
__device__ __forceinline__ void top2_merge(float& z1, int& j1, float& z2, int& j2,
                                           float oz1, int oj1, float oz2, int oj2) {
    bool b1 = (oz1 < z1) || (oz1 == z1 && oj1 < j1);
    if (b1) {
        bool b2 = (z1 < oz2) || (z1 == oz2 && j1 < oj2);
        z2 = b2 ? z1 : oz2; j2 = b2 ? j1 : oj2;
        z1 = oz1; j1 = oj1;
    } else {
        bool b2 = (oz1 < z2) || (oz1 == z2 && oj1 < j2);
        z2 = b2 ? oz1 : z2; j2 = b2 ? oj1 : j2;
    }
}

// ============================================================
// Kernel 1: W only. Warp per row: wsq + fp16 blocked swizzled copy.
// ============================================================
__global__ void ker_wx(const float* __restrict__ W,
                       const int*  __restrict__ itp) {
    if (blockIdx.x == 0 && threadIdx.x == 0) {
        int it = itp[0];
        double TAU   = 20.0 / log(64.0);
        double sigma = 64.0 * exp(-(double)it / TAU);
        g_sched[0] = (float)(2.0 * sigma * sigma);
        g_sched[1] = (float)(0.5 * exp(-(double)it / 20.0));
    }
    int warp = (blockIdx.x * blockDim.x + threadIdx.x) >> 5;
    int lane = threadIdx.x & 31;
    if (warp >= MN) return;

    const float* src = W + (size_t)warp * KDIM;
    float4 v0 = *(const float4*)(src + lane * 8);
    float4 v1 = *(const float4*)(src + lane * 8 + 4);
    uint4 hv;
    hv.x = pk2h(__float2half_rn(v0.x), __float2half_rn(v0.y));
    hv.y = pk2h(__float2half_rn(v0.z), __float2half_rn(v0.w));
    hv.z = pk2h(__float2half_rn(v1.x), __float2half_rn(v1.y));
    hv.w = pk2h(__float2half_rn(v1.z), __float2half_rn(v1.w));

    int jr = warp & 127;
    int bid = (warp >> 7) * 2 + (lane >> 4);
    int col16 = lane & 15;
    int sw = col16 ^ (jr & 7);
    *(uint4*)(g_wblk + (size_t)bid * 32768 + jr * 256 + sw * 16) = hv;
    float s = v0.x*v0.x + v0.y*v0.y + v0.z*v0.z + v0.w*v0.w
            + v1.x*v1.x + v1.y*v1.y + v1.z*v1.z + v1.w*v1.w;
#pragma unroll
    for (int o = 16; o > 0; o >>= 1) s += __shfl_down_sync(0xffffffffu, s, o);
    if (lane == 0) g_wsq[warp] = s;
}

// ============================================================
// Kernel 1c: X -> (a) transposed fp16 blocked (numer) and
// (b) row-major fp16 blocked (dist), both pre-swizzled.
// ============================================================
__global__ void ker_prep(const float* __restrict__ X) {
    __shared__ float t[64][65];
    int bt = blockIdx.x;          // b block (64)
    int dt = blockIdx.y;          // d quarter (64)
    int tid = threadIdx.x;
#pragma unroll
    for (int s = 0; s < 16; s++) {
        int e = tid + 256 * s;
        int b = e >> 6, d = e & 63;
        t[b][d] = X[(size_t)(bt * 64 + b) * KDIM + dt * 64 + d];
    }
    __syncthreads();

    // (a) transposed hi for numer
    char* bhi = g_xbhi + (size_t)bt * 32768;
#pragma unroll
    for (int s = 0; s < 8; s++) {
        int p = tid + 256 * s;
        int d = p >> 5, bp = p & 31;
        float a0 = t[bp * 2][d], a1 = t[bp * 2 + 1][d];
        __half h0 = __float2half_rn(a0);
        __half h1 = __float2half_rn(a1);
        int dg = dt * 64 + d;
        int br = bp * 2;
        uint32_t off = dg * 128 + (((br >> 3) ^ (dg & 7)) << 4) + (br & 7) * 2;
        *(uint32_t*)(bhi + off) = pk2h(h0, h1);
    }

    // (b) row-major fp16 blocked for dist (512B rows, XOR-swizzled)
    char* bxk = g_xbk + (size_t)bt * 32768;
#pragma unroll
    for (int s = 0; s < 2; s++) {
        int i = tid + 256 * s;           // 512 items: 64 b x 8 col16-local
        int b = i >> 3, c8 = i & 7;
        const float* tr = &t[b][c8 * 8];
        uint4 hv;
        hv.x = pk2h(__float2half_rn(tr[0]), __float2half_rn(tr[1]));
        hv.y = pk2h(__float2half_rn(tr[2]), __float2half_rn(tr[3]));
        hv.z = pk2h(__float2half_rn(tr[4]), __float2half_rn(tr[5]));
        hv.w = pk2h(__float2half_rn(tr[6]), __float2half_rn(tr[7]));
        int col16 = dt * 8 + c8;
        *(uint4*)(bxk + b * 512 + ((col16 ^ (b & 7)) << 4)) = hv;
    }
}

// ============================================================
// Kernel 2: approx distance GEMM (hh-only fp16 HMMA) + top-2.
// (unchanged from R15)
// ============================================================
#define XS_ROW    512
#define OFF_WBUF  (256 * XS_ROW)             // 131072
#define WSTAGE    32768
#define OFF_WSQ   (OFF_WBUF + 2 * WSTAGE)    // 196608
#define OFF_MBAR  (OFF_WSQ + 16384)          // 212992
#define DIST_SMEM (OFF_MBAR + 64)            // 213056

__global__ void __launch_bounds__(512, 1)
ker_dist_mma() {
    char* base = (char*)sm;
    uint32_t sbase = smem_u32(base);
    const int tid  = threadIdx.x;
    const int lane = tid & 31;
    const int wid  = tid >> 5;
    const int wb   = wid >> 2;
    const int wj   = wid & 3;
    const int g    = lane >> 2;
    const int c2   = (lane & 3) * 2;
    const int bblk = blockIdx.x * 4;
    const int b0   = blockIdx.x * 256;
    const int quar = blockIdx.y;
    const int jbase = quar * 4096;

    const int la15 = lane & 15;
    const int laKA16 = lane >> 4;
    const int laRB = (lane & 7) + ((lane >> 4) << 3);
    const int laKB16 = (lane >> 3) & 1;

    if (tid == 0) {
        mbar_init(sbase + OFF_MBAR, 1);
        mbar_init(sbase + OFF_MBAR + 8, 1);
        mbar_init(sbase + OFF_MBAR + 16, 1);
    }
#pragma unroll
    for (int t = 0; t < 2; t++) {
        int i = tid + 512 * t;
        *(uint4*)(base + OFF_WSQ + i * 16) =
            *(const uint4*)((const char*)(g_wsq + jbase) + i * 16);
    }
    const float* swsq = (const float*)(base + OFF_WSQ);
    __syncthreads();

    if (tid == 0) {
        uint32_t mbx = sbase + OFF_MBAR + 16;
        mbar_expect(mbx, 4 * 32768);
#pragma unroll
        for (int i = 0; i < 4; i++)
            bulk_g2s(sbase + (uint32_t)i * 32768,
                     g_xbk + (size_t)(bblk + i) * 32768, 32768, mbx);
        uint32_t mb = sbase + OFF_MBAR;
        mbar_expect(mb, WSTAGE);
        bulk_g2s(sbase + OFF_WBUF, g_wblk + (size_t)(quar * 64) * WSTAGE,
                 WSTAGE, mb);
    }

    float z1[8], z2[8];
    int   j1[8], j2[8];
#pragma unroll
    for (int i = 0; i < 8; i++) { z1[i] = z2[i] = FLT_MAX; j1[i] = j2[i] = MN; }

    mbar_wait(sbase + OFF_MBAR + 16, 0);

    float acc[4][4][4];

    for (int ci = 0; ci < 64; ci++) {
        const int jt = ci >> 1, kc = ci & 1;

        mbar_wait(sbase + OFF_MBAR + (uint32_t)(ci & 1) * 8, (ci >> 1) & 1);
        __syncthreads();
        if (tid == 0 && ci + 1 < 64) {
            uint32_t mb = sbase + OFF_MBAR + (uint32_t)((ci + 1) & 1) * 8;
            mbar_expect(mb, WSTAGE);
            bulk_g2s(sbase + OFF_WBUF + (uint32_t)((ci + 1) & 1) * WSTAGE,
                     g_wblk + (size_t)(quar * 64 + ci + 1) * WSTAGE, WSTAGE, mb);
        }

        if (kc == 0) {
#pragma unroll
            for (int bt = 0; bt < 4; bt++)
#pragma unroll
                for (int nt = 0; nt < 4; nt++)
#pragma unroll
                    for (int r = 0; r < 4; r++) acc[bt][nt][r] = 0.f;
        }

        const uint32_t wboff = sbase + OFF_WBUF + (uint32_t)(ci & 1) * WSTAGE;
#pragma unroll
        for (int ks = 0; ks < 8; ks++) {
            uint32_t ah[4][4];
            const int col16A = kc * 16 + ks * 2 + laKA16;
#pragma unroll
            for (int bt = 0; bt < 4; bt++) {
                int row = wb * 64 + bt * 16 + la15;
                uint32_t ra = sbase + row * XS_ROW
                            + (uint32_t)((col16A ^ (row & 7)) << 4);
                ldsm_x4(ah[bt][0], ah[bt][1], ah[bt][2], ah[bt][3], ra);
            }
            uint32_t bh[2][4];
            const int col16B = ks * 2 + laKB16;
#pragma unroll
            for (int ntp = 0; ntp < 2; ntp++) {
                int row = wj * 32 + ntp * 16 + laRB;
                uint32_t rb = wboff + row * 256 + (uint32_t)((col16B ^ (row & 7)) << 4);
                ldsm_x4(bh[ntp][0], bh[ntp][1], bh[ntp][2], bh[ntp][3], rb);
            }
#pragma unroll
            for (int ntp = 0; ntp < 2; ntp++)
#pragma unroll
                for (int bt = 0; bt < 4; bt++) {
                    mma_f16(acc[bt][ntp*2],   ah[bt][0], ah[bt][1], ah[bt][2], ah[bt][3], bh[ntp][0], bh[ntp][1]);
                    mma_f16(acc[bt][ntp*2+1], ah[bt][0], ah[bt][1], ah[bt][2], ah[bt][3], bh[ntp][2], bh[ntp][3]);
                }
        }

        if (kc == 1) {
            const int j0 = jt * 128 + wj * 32;
#pragma unroll
            for (int nt = 0; nt < 4; nt++) {
                int jg = j0 + nt * 8 + c2;
                float w0 = swsq[jg];
                float w1 = swsq[jg + 1];
#pragma unroll
                for (int bt = 0; bt < 4; bt++) {
                    float za0 = fmaf(-2.f, acc[bt][nt][0], w0);
                    float zb0 = fmaf(-2.f, acc[bt][nt][1], w1);
                    float za1 = fmaf(-2.f, acc[bt][nt][2], w0);
                    float zb1 = fmaf(-2.f, acc[bt][nt][3], w1);
                    int s0 = bt * 2, s1 = bt * 2 + 1;
                    if (fminf(za0, zb0) < z2[s0]) {
                        t2_ins(za0, jg,     z1[s0], j1[s0], z2[s0], j2[s0]);
                        t2_ins(zb0, jg + 1, z1[s0], j1[s0], z2[s0], j2[s0]);
                    }
                    if (fminf(za1, zb1) < z2[s1]) {
                        t2_ins(za1, jg,     z1[s1], j1[s1], z2[s1], j2[s1]);
                        t2_ins(zb1, jg + 1, z1[s1], j1[s1], z2[s1], j2[s1]);
                    }
                }
            }
        }
    }

#pragma unroll
    for (int i = 0; i < 8; i++) {
#pragma unroll
        for (int off = 1; off <= 2; off <<= 1) {
            float oz1 = __shfl_xor_sync(0xffffffffu, z1[i], off);
            int   oj1 = __shfl_xor_sync(0xffffffffu, j1[i], off);
            float oz2 = __shfl_xor_sync(0xffffffffu, z2[i], off);
            int   oj2 = __shfl_xor_sync(0xffffffffu, j2[i], off);
            top2_merge(z1[i], j1[i], z2[i], j2[i], oz1, oj1, oz2, oj2);
        }
    }

    __syncthreads();
    float* sz1 = (float*)(base + OFF_WBUF);
    int*   sj1 = (int*)(base + OFF_WBUF + 4096);
    float* sz2 = (float*)(base + OFF_WBUF + 8192);
    int*   sj2 = (int*)(base + OFF_WBUF + 12288);
    if ((lane & 3) == 0) {
#pragma unroll
        for (int i = 0; i < 8; i++) {
            int bt = i >> 1, h = i & 1;
            int row = wb * 64 + bt * 16 + g + 8 * h;
            sz1[row * 4 + wj] = z1[i];
            sj1[row * 4 + wj] = j1[i];
            sz2[row * 4 + wj] = z2[i];
            sj2[row * 4 + wj] = j2[i];
        }
    }
    __syncthreads();
    if (tid < 256) {
        float a1 = sz1[tid * 4], a2 = sz2[tid * 4];
        int   i1 = sj1[tid * 4], i2 = sj2[tid * 4];
        for (int t = 1; t < 4; t++)
            top2_merge(a1, i1, a2, i2,
                       sz1[tid * 4 + t], sj1[tid * 4 + t],
                       sz2[tid * 4 + t], sj2[tid * 4 + t]);
        int gb = quar * BSZ + b0 + tid;
        g_cj[gb * 2]     = jbase + i1;
        g_cj[gb * 2 + 1] = jbase + i2;
    }
}

// ============================================================
// Kernel 2b: exact fp32 re-evaluation of <=8 BMU candidates.
// ============================================================
__global__ void ker_fix(const float* __restrict__ X,
                        const float* __restrict__ W) {
    int b    = blockIdx.x * 8 + (threadIdx.x >> 5);
    int lane = threadIdx.x & 31;

    int cand[8];
#pragma unroll
    for (int q = 0; q < 4; q++) {
        cand[q * 2]     = g_cj[((size_t)q * BSZ + b) * 2];
        cand[q * 2 + 1] = g_cj[((size_t)q * BSZ + b) * 2 + 1];
    }

    const float* xb = X + (size_t)b * KDIM;
    float x[8];
#pragma unroll
    for (int t = 0; t < 8; t++) x[t] = xb[lane * 8 + t];

    float bestz = FLT_MAX;
    int   bestj = MN;
#pragma unroll
    for (int c = 0; c < 8; c++) {
        int j = cand[c];
        const float* wj = W + (size_t)j * KDIM;
        float s = 0.f;
#pragma unroll
        for (int t = 0; t < 8; t++) s += x[t] * wj[lane * 8 + t];
#pragma unroll
        for (int o = 16; o > 0; o >>= 1) s += __shfl_down_sync(0xffffffffu, s, o);
        if (lane == 0) {
            float z = fmaf(-2.f, s, g_wsq[j]);
            if (z < bestz || (z == bestz && j < bestj)) { bestz = z; bestj = j; }
        }
    }
    if (lane == 0) g_bmu[b] = bestj;
}

// ============================================================
// Kernel 3: neighborhood factors (fp16) from exact BMU
// ============================================================
__global__ void ker_pxpy() {
    int i = blockIdx.x;
    float d  = g_sched[0];
    float lr = g_sched[1];
    float fi = (float)i;
    for (int b = threadIdx.x; b < BSZ; b += 256) {
        int bmu = g_bmu[b];
        float dr = fi - (float)(bmu >> 7);
        float dc = fi - (float)(bmu & 127);
        g_pxTh[(size_t)i * BSZ + b] = __float2half_rn(expf(-(dr * dr) / d));
        g_pyTh[(size_t)i * BSZ + b] = __float2half_rn(lr * expf(-(dc * dc) / d));
    }
}

// ============================================================
// Kernel 4: numer (fp16 HMMA, 1 term: a*x_hi) + fused denom.
// denom sums the same rounded a (self-consistent weighting).
// X^T hi streamed via cp.async.bulk, double-buffered.
// ============================================================
#define N_ROWA   144
#define N_ABUF   (128 * N_ROWA)              // 18432
#define XBLK     32768
#define OFF_DSUM 0
#define OFF_NMB  512
#define OFF_A0   1024
#define OFF_X0   (OFF_A0 + 2 * N_ABUF)       // 37888
#define NUMER_SMEM (OFF_X0 + 2 * XBLK)       // 103424

__global__ void __launch_bounds__(512, 1)
ker_numer_tc(const float* __restrict__ Wold, float* __restrict__ OUT) {
    char* base = (char*)sm;
    uint32_t sbase = smem_u32(base);
    float* dsum = (float*)(base + OFF_DSUM);

    const int tid  = threadIdx.x;
    const int wid  = tid >> 5;
    const int lane = tid & 31;
    const int m    = blockIdx.x;

    const int n0 = (wid >> 2) * 32;
    const int d0 = (wid & 3) * 64;
    const int g  = lane >> 2;
    const int c2 = (lane & 3) * 2;

    const int la15 = lane & 15;
    const int laKA = (lane >> 4) << 4;
    const int laRB = (lane & 7) + ((lane >> 4) << 3);
    const int laKB16 = (lane >> 3) & 1;

    if (tid < 128) dsum[tid] = 0.f;
    if (tid == 0) {
        mbar_init(sbase + OFF_NMB, 1);
        mbar_init(sbase + OFF_NMB + 8, 1);
    }

    float acc[2][8][4];
#pragma unroll
    for (int mt = 0; mt < 2; mt++)
#pragma unroll
        for (int nt = 0; nt < 8; nt++)
#pragma unroll
            for (int r = 0; r < 4; r++) acc[mt][nt][r] = 0.f;

    const int bg = tid & 7;
    const int nrow = tid >> 3;
    float dden[2] = {0.f, 0.f};

#define NUMER_XISSUE(ch) do {                                                  \
        uint32_t mb = sbase + OFF_NMB + (uint32_t)((ch) & 1) * 8;              \
        uint32_t xb = sbase + OFF_X0 + (uint32_t)((ch) & 1) * XBLK;            \
        mbar_expect(mb, XBLK);                                                 \
        bulk_g2s(xb, g_xbhi + (size_t)(ch) * XBLK, XBLK, mb);                  \
    } while (0)

#define NUMER_LDG(ch, pxv, py0, py1) do {                                      \
        size_t bo = (size_t)((ch) * 64 + bg * 8) * 2;                          \
        pxv = *(const uint4*)((const char*)(g_pxTh + (size_t)m * BSZ) + bo);   \
        py0 = *(const uint4*)((const char*)(g_pyTh + (size_t)nrow * BSZ) + bo);\
        py1 = *(const uint4*)((const char*)(g_pyTh + (size_t)(nrow + 64) * BSZ) + bo); \
    } while (0)

#define NUMER_CONVERT(ch, pxv, py0, py1) do {                                  \
        uint32_t ab = (uint32_t)(OFF_A0 + ((ch) & 1) * N_ABUF);                \
        __half2* pxh = (__half2*)&(pxv);                                       \
        float2 pf[4];                                                          \
        _Pragma("unroll")                                                      \
        for (int k = 0; k < 4; k++) pf[k] = __half22float2(pxh[k]);            \
        _Pragma("unroll")                                                      \
        for (int s = 0; s < 2; s++) {                                          \
            int n = nrow + 64 * s;                                             \
            uint4 pv = s ? (py1) : (py0);                                      \
            __half2* ph = (__half2*)&pv;                                       \
            float ssum = 0.f;                                                  \
            __half h[8];                                                       \
            _Pragma("unroll")                                                  \
            for (int k = 0; k < 4; k++) {                                      \
                float2 yf = __half22float2(ph[k]);                             \
                float a0 = pf[k].x * yf.x;                                     \
                float a1 = pf[k].y * yf.y;                                     \
                h[2*k]   = __float2half_rn(a0);                                \
                h[2*k+1] = __float2half_rn(a1);                                \
                ssum += __half2float(h[2*k]) + __half2float(h[2*k+1]);         \
            }                                                                  \
            dden[s] += ssum;                                                   \
            uint4 hv = make_uint4(pk2h(h[0],h[1]), pk2h(h[2],h[3]),            \
                                  pk2h(h[4],h[5]), pk2h(h[6],h[7]));           \
            *(uint4*)(base + ab + n * N_ROWA + bg * 16) = hv;                  \
        }                                                                      \
    } while (0)

    {
        uint4 pxv, py0, py1;
        NUMER_LDG(0, pxv, py0, py1);
        NUMER_CONVERT(0, pxv, py0, py1);
        __syncthreads();
        if (tid == 0) NUMER_XISSUE(0);
    }

    uint4 pxv, py0, py1;
    for (int ch = 0; ch < 128; ch++) {
        mbar_wait(sbase + OFF_NMB + (uint32_t)(ch & 1) * 8, (ch >> 1) & 1);
        __syncthreads();

        const bool more = (ch + 1 < 128);
        if (more) {
            if (tid == 0) NUMER_XISSUE(ch + 1);
            NUMER_LDG(ch + 1, pxv, py0, py1);
        }

        const uint32_t abase = sbase + OFF_A0 + (uint32_t)(ch & 1) * N_ABUF;
        const uint32_t xbase = sbase + OFF_X0 + (uint32_t)(ch & 1) * XBLK;
#pragma unroll
        for (int ks = 0; ks < 4; ks++) {
            uint32_t ah[2][4];
            const int kbA = ks * 32 + laKA;
#pragma unroll
            for (int bt = 0; bt < 2; bt++) {
                uint32_t ra = abase + (n0 + bt * 16 + la15) * N_ROWA + kbA;
                ldsm_x4(ah[bt][0], ah[bt][1], ah[bt][2], ah[bt][3], ra);
            }
            const int col16 = ks * 2 + laKB16;
#pragma unroll
            for (int h2 = 0; h2 < 2; h2++) {
                uint32_t bh[2][4];
#pragma unroll
                for (int p = 0; p < 2; p++) {
                    int row = d0 + (h2 * 2 + p) * 16 + laRB;
                    uint32_t sw = (uint32_t)((col16 ^ (row & 7)) << 4);
                    ldsm_x4(bh[p][0], bh[p][1], bh[p][2], bh[p][3],
                            xbase + row * 128 + sw);
                }
#pragma unroll
                for (int p = 0; p < 2; p++)
#pragma unroll
                    for (int bt = 0; bt < 2; bt++) {
                        int nt = (h2 * 2 + p) * 2;
                        mma_f16(acc[bt][nt],   ah[bt][0], ah[bt][1], ah[bt][2], ah[bt][3], bh[p][0], bh[p][1]);
                        mma_f16(acc[bt][nt+1], ah[bt][0], ah[bt][1], ah[bt][2], ah[bt][3], bh[p][2], bh[p][3]);
                    }
            }
        }

        if (more) NUMER_CONVERT(ch + 1, pxv, py0, py1);
    }

    __syncthreads();
#pragma unroll
    for (int s = 0; s < 2; s++)
        atomicAdd(&dsum[nrow + 64 * s], dden[s]);
    __syncthreads();

#pragma unroll
    for (int mt = 0; mt < 2; mt++) {
#pragma unroll
        for (int gg = 0; gg < 2; gg++) {
            int n = n0 + mt * 16 + g + gg * 8;
            float den = dsum[n];
            size_t rb = ((size_t)(m * 128 + n)) * KDIM;
#pragma unroll
            for (int nt = 0; nt < 8; nt++) {
                int dcol = d0 + nt * 8 + c2;
                float v0 = acc[mt][nt][gg * 2];
                float v1 = acc[mt][nt][gg * 2 + 1];
                float2 o;
                if (den != 0.f) {
                    o.x = v0 / den; o.y = v1 / den;
                } else {
                    o.x = Wold[rb + dcol]; o.y = Wold[rb + dcol + 1];
                }
                *(float2*)(OUT + rb + dcol) = o;
            }
        }
    }
}

// ============================================================
extern "C" void kernel_launch(void* const* d_in, const int* in_sizes, int n_in,
                              void* d_out, int out_size) {
    (void)in_sizes; (void)n_in; (void)out_size;
    const float* data    = (const float*)d_in[0];
    const float* weights = (const float*)d_in[1];
    const int*   itp     = (const int*)d_in[2];
    float*       out     = (float*)d_out;

    cudaFuncSetAttribute(ker_dist_mma, cudaFuncAttributeMaxDynamicSharedMemorySize,
                         DIST_SMEM);
    cudaFuncSetAttribute(ker_numer_tc, cudaFuncAttributeMaxDynamicSharedMemorySize,
                         NUMER_SMEM);

    ker_wx<<<MN / 8, 256>>>(weights, itp);
    ker_prep<<<dim3(BSZ / 64, KDIM / 64), 256>>>(data);
    ker_dist_mma<<<dim3(32, 4), 512, DIST_SMEM>>>();
    ker_fix<<<BSZ / 8, 256>>>(data, weights);
    ker_pxpy<<<128, 256>>>();
    ker_numer_tc<<<128, 512, NUMER_SMEM>>>(weights, out);
}